// round 3
// baseline (speedup 1.0000x reference)
#include <cuda_runtime.h>
#include <mma.h>
#include <math.h>

using namespace nvcuda;

#define TT 256      // timesteps
#define BB 256      // batch
#define DD 1024     // hidden dim
#define WS 2048     // W row stride (W is (D, 2D) row-major)

// ===========================================================================
// Kernel 1: preactivations, tf32 wmma, 128x128 tile, double-buffered.
//   out[(b*TT + t)*DD + d] = bias[d] + sum_k x[(t*BB+b)*DD + k] * W[d*WS + k]
// ===========================================================================
#define X_BM 128
#define X_BN 128
#define X_BK 32
#define X_LD 40                       // padded smem ldm
#define X_TILE (X_BM * X_LD)          // 5120 floats
#define X_SMEM_FLOATS (4 * X_TILE)    // A0,B0,A1,B1 = 20480 floats (80 KB)

__global__ void __launch_bounds__(256)
gemm_x_tf32(const float* __restrict__ x, const float* __restrict__ W,
            const float* __restrict__ bias, float* __restrict__ out)
{
    extern __shared__ float sm[];
    float* sA[2] = { sm,              sm + 2 * X_TILE };
    float* sB[2] = { sm + X_TILE,     sm + 3 * X_TILE };

    const int r0  = blockIdx.y * X_BM;   // row tile in (t*BB + b) space
    const int d0  = blockIdx.x * X_BN;
    const int tid = threadIdx.x;
    const int wid = tid >> 5;
    const int warpM = wid & 3;           // 4 x 32 rows
    const int warpN = wid >> 2;          // 2 x 64 cols

    wmma::fragment<wmma::accumulator, 16, 16, 8, float> acc[2][4];
    #pragma unroll
    for (int mi = 0; mi < 2; ++mi)
        #pragma unroll
        for (int ni = 0; ni < 4; ++ni)
            wmma::fill_fragment(acc[mi][ni], 0.0f);

    // loader: 4 float4/thread per tile per chunk
    auto load_chunk = [&](int k0, float* dA, float* dB) {
        #pragma unroll
        for (int j = 0; j < 4; ++j) {
            int f   = tid + j * 256;     // 1024 float4
            int row = f >> 3;            // 8 float4 per row (32 floats)
            int c4  = f & 7;
            float4 va = *reinterpret_cast<const float4*>(
                &x[(size_t)(r0 + row) * DD + k0 + c4 * 4]);
            float* pa = &dA[row * X_LD + c4 * 4];
            pa[0] = wmma::__float_to_tf32(va.x);
            pa[1] = wmma::__float_to_tf32(va.y);
            pa[2] = wmma::__float_to_tf32(va.z);
            pa[3] = wmma::__float_to_tf32(va.w);
            float4 vb = *reinterpret_cast<const float4*>(
                &W[(size_t)(d0 + row) * WS + k0 + c4 * 4]);
            float* pb = &dB[row * X_LD + c4 * 4];
            pb[0] = wmma::__float_to_tf32(vb.x);
            pb[1] = wmma::__float_to_tf32(vb.y);
            pb[2] = wmma::__float_to_tf32(vb.z);
            pb[3] = wmma::__float_to_tf32(vb.w);
        }
    };

    load_chunk(0, sA[0], sB[0]);
    __syncthreads();

    const int NCH = DD / X_BK;           // 32 chunks
    for (int c = 0; c < NCH; ++c) {
        int cur = c & 1;
        if (c + 1 < NCH) load_chunk((c + 1) * X_BK, sA[cur ^ 1], sB[cur ^ 1]);

        #pragma unroll
        for (int kk = 0; kk < X_BK; kk += 8) {
            wmma::fragment<wmma::matrix_a, 16, 16, 8, wmma::precision::tf32, wmma::row_major> a[2];
            #pragma unroll
            for (int mi = 0; mi < 2; ++mi)
                wmma::load_matrix_sync(a[mi], &sA[cur][(warpM * 32 + mi * 16) * X_LD + kk], X_LD);
            #pragma unroll
            for (int ni = 0; ni < 4; ++ni) {
                wmma::fragment<wmma::matrix_b, 16, 16, 8, wmma::precision::tf32, wmma::col_major> b;
                wmma::load_matrix_sync(b, &sB[cur][(warpN * 64 + ni * 16) * X_LD + kk], X_LD);
                #pragma unroll
                for (int mi = 0; mi < 2; ++mi)
                    wmma::mma_sync(acc[mi][ni], a[mi], b, acc[mi][ni]);
            }
        }
        __syncthreads();
    }

    // Stage C in smem (alias the buffers: 16384 <= 20480 floats)
    float* sC = sm;
    #pragma unroll
    for (int mi = 0; mi < 2; ++mi)
        #pragma unroll
        for (int ni = 0; ni < 4; ++ni)
            wmma::store_matrix_sync(&sC[(warpM * 32 + mi * 16) * X_BN + warpN * 64 + ni * 16],
                                    acc[mi][ni], X_BN, wmma::mem_row_major);
    __syncthreads();

    // Epilogue: +bias, scatter. Block spans 128 rows => t constant, b = (r0&255)+row
    const int t = r0 >> 8;
    const int bbase = r0 & 255;
    #pragma unroll
    for (int j = 0; j < 16; ++j) {
        int f   = tid + j * 256;         // 4096 float4
        int row = f >> 5;                // 32 float4 per row
        int c4  = f & 31;
        float4 bv = *reinterpret_cast<const float4*>(&bias[d0 + c4 * 4]);
        const float* cp = &sC[row * X_BN + c4 * 4];
        float4 o;
        o.x = cp[0] + bv.x; o.y = cp[1] + bv.y; o.z = cp[2] + bv.z; o.w = cp[3] + bv.w;
        *reinterpret_cast<float4*>(
            &out[((size_t)((bbase + row) * TT + t)) * DD + d0 + c4 * 4]) = o;
    }
}

// ===========================================================================
// Kernel 2: persistent recurrence, Wh resident in smem.
// Block owns (b0..b0+63) x (d0..d0+31). Wh stripe 32x1024 fp32 lives in smem
// for all 256 steps. h tiles double-buffered from L2. 4 K-split accumulators.
// ===========================================================================
#define R_BM 64
#define R_BN 32
#define R_BK 128
#define R_ALD 136                       // A ldm (128 + 8)
#define R_WLD 1032                      // Wh ldm (1024 + 8)
#define R_NBLK 128
// smem layout (floats): Wh[32*1032]=33024 | A0[64*136]=8704 | A1=8704 | C[64*32]=2048
#define R_OFF_A0 (R_BN * R_WLD)
#define R_OFF_A1 (R_OFF_A0 + R_BM * R_ALD)
#define R_OFF_C  (R_OFF_A1 + R_BM * R_ALD)
#define R_SMEM_FLOATS (R_OFF_C + R_BM * R_BN)   // 52480 floats = 209920 B

__device__ unsigned g_cnt = 0;
__device__ unsigned g_phase = 0;   // monotonic across graph replays

__global__ void __launch_bounds__(256)
rnn_persistent(const float* __restrict__ W, float* __restrict__ out)
{
    extern __shared__ float sm[];
    float* sWh  = sm;
    float* sA[2] = { sm + R_OFF_A0, sm + R_OFF_A1 };
    float* sC   = sm + R_OFF_C;
    __shared__ unsigned s_base;

    const int tid = threadIdx.x;
    const int wid = tid >> 5;
    const int warpM = wid >> 1;      // 4 x 16 rows (M=64)
    const int warpN = wid & 1;       // 2 x 16 cols (N=32)

    const int nT = blockIdx.x & 31;  // 32 d-stripes
    const int mT = blockIdx.x >> 5;  // 4 batch groups
    const int d0 = nT * R_BN;
    const int b0 = mT * R_BM;

    // Load Wh stripe once, tf32-rounded: sWh[n][k], n=0..31, k=0..1023
    {
        const float* Wh = W + DD;
        #pragma unroll
        for (int j = 0; j < 32; ++j) {
            int f   = tid + j * 256;     // 8192 float4
            int row = f >> 8;            // 256 float4 per row
            int c4  = f & 255;
            float4 v = *reinterpret_cast<const float4*>(
                &Wh[(size_t)(d0 + row) * WS + c4 * 4]);
            float* p = &sWh[row * R_WLD + c4 * 4];
            p[0] = wmma::__float_to_tf32(v.x);
            p[1] = wmma::__float_to_tf32(v.y);
            p[2] = wmma::__float_to_tf32(v.z);
            p[3] = wmma::__float_to_tf32(v.w);
        }
    }

    if (tid == 0) s_base = *(volatile unsigned*)&g_phase;
    __syncthreads();
    const unsigned base = s_base;

    // h-tile loader: 8 float4/thread, via L2 (peers wrote it)
    auto load_h = [&](int tprev, int chunk, float* dst) {
        #pragma unroll
        for (int j = 0; j < 8; ++j) {
            int f   = tid + j * 256;     // 2048 float4
            int row = f >> 5;            // 32 float4 per row
            int c4  = f & 31;
            float4 v = __ldcg(reinterpret_cast<const float4*>(
                &out[((size_t)((b0 + row) * TT + tprev)) * DD + chunk * R_BK + c4 * 4]));
            float* p = &dst[row * R_ALD + c4 * 4];
            p[0] = wmma::__float_to_tf32(v.x);
            p[1] = wmma::__float_to_tf32(v.y);
            p[2] = wmma::__float_to_tf32(v.z);
            p[3] = wmma::__float_to_tf32(v.w);
        }
    };

    for (int t = 0; t < TT; ++t) {
        if (t == 0) {
            // h0 = 0: out slice = tanh(preact)
            #pragma unroll
            for (int j = 0; j < 2; ++j) {
                int f   = tid + j * 256;     // 512 float4
                int row = f >> 3;            // 8 float4 per row
                int c4  = f & 7;
                float* p = &out[((size_t)((b0 + row) * TT + 0)) * DD + d0 + c4 * 4];
                float4 v = __ldcg(reinterpret_cast<const float4*>(p));
                v.x = tanhf(v.x); v.y = tanhf(v.y); v.z = tanhf(v.z); v.w = tanhf(v.w);
                *reinterpret_cast<float4*>(p) = v;
            }
        } else {
            wmma::fragment<wmma::accumulator, 16, 16, 8, float> acc[4];
            #pragma unroll
            for (int i = 0; i < 4; ++i) wmma::fill_fragment(acc[i], 0.0f);

            load_h(t - 1, 0, sA[0]);
            __syncthreads();

            #pragma unroll
            for (int c = 0; c < DD / R_BK; ++c) {    // 8 chunks
                int cur = c & 1;
                if (c + 1 < DD / R_BK) load_h(t - 1, c + 1, sA[cur ^ 1]);

                const float* bbase_p = &sWh[warpN * 16 * R_WLD + c * R_BK];
                const float* abase_p = &sA[cur][warpM * 16 * R_ALD];
                #pragma unroll
                for (int kk = 0; kk < R_BK; kk += 8) {
                    wmma::fragment<wmma::matrix_a, 16, 16, 8, wmma::precision::tf32, wmma::row_major> a;
                    wmma::fragment<wmma::matrix_b, 16, 16, 8, wmma::precision::tf32, wmma::col_major> b;
                    wmma::load_matrix_sync(a, abase_p + kk, R_ALD);
                    wmma::load_matrix_sync(b, bbase_p + kk, R_WLD);
                    wmma::mma_sync(acc[(kk >> 3) & 3], a, b, acc[(kk >> 3) & 3]);
                }
                __syncthreads();
            }

            // Reduce K-split accumulators
            #pragma unroll
            for (int i = 1; i < 4; ++i)
                #pragma unroll
                for (int e = 0; e < acc[0].num_elements; ++e)
                    acc[0].x[e] += acc[i].x[e];

            wmma::store_matrix_sync(&sC[(warpM * 16) * R_BN + warpN * 16], acc[0],
                                    R_BN, wmma::mem_row_major);
            __syncthreads();

            // Epilogue: + preact, tanh, store in place
            #pragma unroll
            for (int j = 0; j < 2; ++j) {
                int f   = tid + j * 256;     // 512 float4
                int row = f >> 3;
                int c4  = f & 7;
                float* p = &out[((size_t)((b0 + row) * TT + t)) * DD + d0 + c4 * 4];
                float4 pre = __ldcg(reinterpret_cast<const float4*>(p));
                const float* cp = &sC[row * R_BN + c4 * 4];
                float4 o;
                o.x = tanhf(pre.x + cp[0]);
                o.y = tanhf(pre.y + cp[1]);
                o.z = tanhf(pre.z + cp[2]);
                o.w = tanhf(pre.w + cp[3]);
                *reinterpret_cast<float4*>(p) = o;
            }
        }

        // Grid barrier (skip after last step). g_cnt returns to 0, g_phase
        // monotonic -> deterministic across graph replays.
        if (t != TT - 1) {
            __syncthreads();
            if (tid == 0) {
                __threadfence();
                unsigned old = atomicAdd(&g_cnt, 1);
                if (old == R_NBLK - 1) {
                    atomicExch(&g_cnt, 0);
                    __threadfence();
                    atomicAdd(&g_phase, 1);
                } else {
                    unsigned target = base + (unsigned)(t + 1);
                    while (*(volatile unsigned*)&g_phase < target) { }
                    __threadfence();
                }
            }
            __syncthreads();
        }
    }
}

// ===========================================================================
// Launch
// ===========================================================================
extern "C" void kernel_launch(void* const* d_in, const int* in_sizes, int n_in,
                              void* d_out, int out_size)
{
    const float* x    = (const float*)d_in[0];
    const float* W    = (const float*)d_in[1];
    const float* bias = (const float*)d_in[2];
    float* out = (float*)d_out;

    cudaFuncSetAttribute(gemm_x_tf32, cudaFuncAttributeMaxDynamicSharedMemorySize,
                         X_SMEM_FLOATS * sizeof(float));
    cudaFuncSetAttribute(rnn_persistent, cudaFuncAttributeMaxDynamicSharedMemorySize,
                         R_SMEM_FLOATS * sizeof(float));

    dim3 g1(DD / X_BN, (TT * BB) / X_BM);   // (8, 512)
    gemm_x_tf32<<<g1, 256, X_SMEM_FLOATS * sizeof(float)>>>(x, W, bias, out);

    rnn_persistent<<<R_NBLK, 256, R_SMEM_FLOATS * sizeof(float)>>>(W, out);
}

// round 4
// speedup vs baseline: 1.5894x; 1.5894x over previous
#include <cuda_runtime.h>
#include <mma.h>
#include <math.h>

using namespace nvcuda;

#define TT 256      // timesteps
#define BB 256      // batch
#define DD 1024     // hidden dim
#define WS 2048     // W row stride (W is (D, 2D) row-major)

// ===========================================================================
// Kernel 1: preactivations, tf32 wmma, 128x128 tile, double-buffered.
//   out[(b*TT + t)*DD + d] = bias[d] + sum_k x[(t*BB+b)*DD + k] * W[d*WS + k]
// ===========================================================================
#define X_BM 128
#define X_BN 128
#define X_BK 32
#define X_LD 40                       // padded smem ldm
#define X_TILE (X_BM * X_LD)          // 5120 floats
#define X_SMEM_FLOATS (4 * X_TILE)    // A0,B0,A1,B1 = 20480 floats (80 KB)

__global__ void __launch_bounds__(256)
gemm_x_tf32(const float* __restrict__ x, const float* __restrict__ W,
            const float* __restrict__ bias, float* __restrict__ out)
{
    extern __shared__ float sm[];
    float* sA[2] = { sm,              sm + 2 * X_TILE };
    float* sB[2] = { sm + X_TILE,     sm + 3 * X_TILE };

    const int r0  = blockIdx.y * X_BM;   // row tile in (t*BB + b) space
    const int d0  = blockIdx.x * X_BN;
    const int tid = threadIdx.x;
    const int wid = tid >> 5;
    const int warpM = wid & 3;           // 4 x 32 rows
    const int warpN = wid >> 2;          // 2 x 64 cols

    wmma::fragment<wmma::accumulator, 16, 16, 8, float> acc[2][4];
    #pragma unroll
    for (int mi = 0; mi < 2; ++mi)
        #pragma unroll
        for (int ni = 0; ni < 4; ++ni)
            wmma::fill_fragment(acc[mi][ni], 0.0f);

    auto load_chunk = [&](int k0, float* dA, float* dB) {
        #pragma unroll
        for (int j = 0; j < 4; ++j) {
            int f   = tid + j * 256;     // 1024 float4
            int row = f >> 3;            // 8 float4 per row (32 floats)
            int c4  = f & 7;
            float4 va = *reinterpret_cast<const float4*>(
                &x[(size_t)(r0 + row) * DD + k0 + c4 * 4]);
            float* pa = &dA[row * X_LD + c4 * 4];
            pa[0] = wmma::__float_to_tf32(va.x);
            pa[1] = wmma::__float_to_tf32(va.y);
            pa[2] = wmma::__float_to_tf32(va.z);
            pa[3] = wmma::__float_to_tf32(va.w);
            float4 vb = *reinterpret_cast<const float4*>(
                &W[(size_t)(d0 + row) * WS + k0 + c4 * 4]);
            float* pb = &dB[row * X_LD + c4 * 4];
            pb[0] = wmma::__float_to_tf32(vb.x);
            pb[1] = wmma::__float_to_tf32(vb.y);
            pb[2] = wmma::__float_to_tf32(vb.z);
            pb[3] = wmma::__float_to_tf32(vb.w);
        }
    };

    load_chunk(0, sA[0], sB[0]);
    __syncthreads();

    const int NCH = DD / X_BK;           // 32 chunks
    for (int c = 0; c < NCH; ++c) {
        int cur = c & 1;
        if (c + 1 < NCH) load_chunk((c + 1) * X_BK, sA[cur ^ 1], sB[cur ^ 1]);

        #pragma unroll
        for (int kk = 0; kk < X_BK; kk += 8) {
            wmma::fragment<wmma::matrix_a, 16, 16, 8, wmma::precision::tf32, wmma::row_major> a[2];
            #pragma unroll
            for (int mi = 0; mi < 2; ++mi)
                wmma::load_matrix_sync(a[mi], &sA[cur][(warpM * 32 + mi * 16) * X_LD + kk], X_LD);
            #pragma unroll
            for (int ni = 0; ni < 4; ++ni) {
                wmma::fragment<wmma::matrix_b, 16, 16, 8, wmma::precision::tf32, wmma::col_major> b;
                wmma::load_matrix_sync(b, &sB[cur][(warpN * 64 + ni * 16) * X_LD + kk], X_LD);
                #pragma unroll
                for (int mi = 0; mi < 2; ++mi)
                    wmma::mma_sync(acc[mi][ni], a[mi], b, acc[mi][ni]);
            }
        }
        __syncthreads();
    }

    // Stage C in smem (alias buffers: 16384 <= 20480 floats)
    float* sC = sm;
    #pragma unroll
    for (int mi = 0; mi < 2; ++mi)
        #pragma unroll
        for (int ni = 0; ni < 4; ++ni)
            wmma::store_matrix_sync(&sC[(warpM * 32 + mi * 16) * X_BN + warpN * 64 + ni * 16],
                                    acc[mi][ni], X_BN, wmma::mem_row_major);
    __syncthreads();

    // Epilogue: +bias, scatter. Block spans 128 rows => t constant.
    const int t = r0 >> 8;
    const int bbase = r0 & 255;
    #pragma unroll
    for (int j = 0; j < 16; ++j) {
        int f   = tid + j * 256;         // 4096 float4
        int row = f >> 5;                // 32 float4 per row
        int c4  = f & 31;
        float4 bv = *reinterpret_cast<const float4*>(&bias[d0 + c4 * 4]);
        const float* cp = &sC[row * X_BN + c4 * 4];
        float4 o;
        o.x = cp[0] + bv.x; o.y = cp[1] + bv.y; o.z = cp[2] + bv.z; o.w = cp[3] + bv.w;
        *reinterpret_cast<float4*>(
            &out[((size_t)((bbase + row) * TT + t)) * DD + d0 + c4 * 4]) = o;
    }
}

// ===========================================================================
// Kernel 2: persistent recurrence, R2 tile shape + latency fixes.
// 128 blocks x 512 threads. Block tile: 32 batch x 64 d. BK=64, double
// buffered; 16 warps each own one 16x16 output tile with 4 K-split accs.
// ===========================================================================
#define R_BM 32
#define R_BN 64
#define R_BK 64
#define R_ALD 72
#define R_BLD 72
#define R_ATILE (R_BM * R_ALD)          // 2304
#define R_BTILE (R_BN * R_BLD)          // 4608
#define R_NBLK 128
// smem: A0 | B0 | A1 | B1 | C(32x64)
#define R_OFF_C (2 * (R_ATILE + R_BTILE))
#define R_SMEM_FLOATS (R_OFF_C + R_BM * R_BN)   // 15872 floats = 63.5 KB

__device__ unsigned g_cnt = 0;
__device__ unsigned g_phase = 0;   // monotonic across graph replays

__global__ void __launch_bounds__(512)
rnn_persistent(const float* __restrict__ W, float* __restrict__ out)
{
    extern __shared__ float sm[];
    float* sA[2] = { sm,                    sm + R_ATILE + R_BTILE };
    float* sB[2] = { sm + R_ATILE,          sm + 2 * R_ATILE + R_BTILE };
    float* sC    = sm + R_OFF_C;
    __shared__ unsigned s_base;

    const int tid = threadIdx.x;
    const int wid = tid >> 5;        // 16 warps
    const int warpM = wid & 1;       // 2 x 16 rows
    const int warpN = wid >> 1;      // 8  hmm -> need 4 cols of 16 over BN=64
    // remap: 16 warps = 2(M) x 4(N) x 2(K-half). Each (M,N) pair is handled by
    // two warps splitting the K range; their partials are summed via sC atomically?
    // Simpler: 16 warps = 2(M) x 8(N) won't fit BN=64/16=4. Use 8 compute pairs:
    // warps 0..7 compute, warps 8..15 also compute on other K half.
    const int kHalf = wid >> 3;      // 0 or 1: K range [kHalf*512, kHalf*512+512)
    const int w8    = wid & 7;
    const int wM    = w8 & 1;        // 2 x 16 rows
    const int wN    = w8 >> 1;       // 4 x 16 cols

    const int nT = blockIdx.x & 15;  // 16 d-stripes
    const int mT = blockIdx.x >> 4;  // 8 batch groups
    const int d0 = nT * R_BN;
    const int b0 = mT * R_BM;

    const float* Wh = W + DD;

    if (tid == 0) s_base = *(volatile unsigned*)&g_phase;
    __syncthreads();
    const unsigned base = s_base;

    // loaders: A tile 32x64 = 512 float4 (1/thread); B tile 64x64 = 1024 float4 (2/thread)
    auto load_h = [&](int tprev, int k0, float* dst) {
        int row = tid >> 4;              // 16 float4 per row
        int c4  = tid & 15;
        float4 v = __ldcg(reinterpret_cast<const float4*>(
            &out[((size_t)((b0 + row) * TT + tprev)) * DD + k0 + c4 * 4]));
        float* p = &dst[row * R_ALD + c4 * 4];
        p[0] = wmma::__float_to_tf32(v.x);
        p[1] = wmma::__float_to_tf32(v.y);
        p[2] = wmma::__float_to_tf32(v.z);
        p[3] = wmma::__float_to_tf32(v.w);
    };
    auto load_w = [&](int k0, float* dst) {
        #pragma unroll
        for (int j = 0; j < 2; ++j) {
            int f   = tid + j * 512;
            int row = f >> 4;
            int c4  = f & 15;
            float4 v = *reinterpret_cast<const float4*>(
                &Wh[(size_t)(d0 + row) * WS + k0 + c4 * 4]);
            float* p = &dst[row * R_BLD + c4 * 4];
            p[0] = wmma::__float_to_tf32(v.x);
            p[1] = wmma::__float_to_tf32(v.y);
            p[2] = wmma::__float_to_tf32(v.z);
            p[3] = wmma::__float_to_tf32(v.w);
        }
    };

    for (int t = 0; t < TT; ++t) {
        if (t == 0) {
            // h0 = 0: out tile = tanh(preact). 512 float4, 1/thread.
            int row = tid >> 4;
            int c4  = tid & 15;
            float* p = &out[((size_t)((b0 + row) * TT + 0)) * DD + d0 + c4 * 4];
            float4 v = __ldcg(reinterpret_cast<const float4*>(p));
            v.x = tanhf(v.x); v.y = tanhf(v.y); v.z = tanhf(v.z); v.w = tanhf(v.w);
            *reinterpret_cast<float4*>(p) = v;
        } else {
            wmma::fragment<wmma::accumulator, 16, 16, 8, float> acc[4];
            #pragma unroll
            for (int i = 0; i < 4; ++i) wmma::fill_fragment(acc[i], 0.0f);

            load_h(t - 1, 0, sA[0]);
            load_w(0, sB[0]);
            __syncthreads();

            const int NCH = DD / R_BK;               // 16 chunks
            for (int c = 0; c < NCH; ++c) {
                int cur = c & 1;
                if (c + 1 < NCH) {
                    load_h(t - 1, (c + 1) * R_BK, sA[cur ^ 1]);
                    load_w((c + 1) * R_BK, sB[cur ^ 1]);
                }
                // this warp handles k-range half within the chunk:
                // chunk is 64 wide; kHalf warp takes [kHalf*32, kHalf*32+32)
                const float* ap = &sA[cur][wM * 16 * R_ALD + kHalf * 32];
                const float* bp = &sB[cur][wN * 16 * R_BLD + kHalf * 32];
                #pragma unroll
                for (int kk = 0; kk < 32; kk += 8) {
                    wmma::fragment<wmma::matrix_a, 16, 16, 8, wmma::precision::tf32, wmma::row_major> a;
                    wmma::fragment<wmma::matrix_b, 16, 16, 8, wmma::precision::tf32, wmma::col_major> b;
                    wmma::load_matrix_sync(a, ap + kk, R_ALD);
                    wmma::load_matrix_sync(b, bp + kk, R_BLD);
                    wmma::mma_sync(acc[kk >> 3], a, b, acc[kk >> 3]);
                }
                __syncthreads();
            }

            // Reduce 4 K-split accs within warp
            #pragma unroll
            for (int i = 1; i < 4; ++i)
                #pragma unroll
                for (int e = 0; e < acc[0].num_elements; ++e)
                    acc[0].x[e] += acc[i].x[e];

            // Combine the two K-half warps through sC: kHalf=0 stores, kHalf=1 adds.
            if (kHalf == 0)
                wmma::store_matrix_sync(&sC[(wM * 16) * R_BN + wN * 16], acc[0],
                                        R_BN, wmma::mem_row_major);
            __syncthreads();
            if (kHalf == 1) {
                // accumulate into sC: elements of acc map via store to a temp area?
                // store to private strip then add: reuse sA[0] region as scratch (safe:
                // all loads done this step; next step reloads after barrier).
                float* scratch = sA[0];
                wmma::store_matrix_sync(&scratch[(wM * 16) * R_BN + wN * 16], acc[0],
                                        R_BN, wmma::mem_row_major);
            }
            __syncthreads();
            // Epilogue: sC + scratch + preact -> tanh -> store. 512 float4, 1/thread.
            {
                const float* scratch = sA[0];
                int row = tid >> 4;
                int c4  = tid & 15;
                float* p = &out[((size_t)((b0 + row) * TT + t)) * DD + d0 + c4 * 4];
                float4 pre = __ldcg(reinterpret_cast<const float4*>(p));
                const float* c0 = &sC[row * R_BN + c4 * 4];
                const float* c1 = &scratch[row * R_BN + c4 * 4];
                float4 o;
                o.x = tanhf(pre.x + c0[0] + c1[0]);
                o.y = tanhf(pre.y + c0[1] + c1[1]);
                o.z = tanhf(pre.z + c0[2] + c1[2]);
                o.w = tanhf(pre.w + c0[3] + c1[3]);
                *reinterpret_cast<float4*>(p) = o;
            }
        }

        // Grid barrier (skip after last step)
        if (t != TT - 1) {
            __syncthreads();
            if (tid == 0) {
                __threadfence();
                unsigned old = atomicAdd(&g_cnt, 1);
                if (old == R_NBLK - 1) {
                    atomicExch(&g_cnt, 0);
                    __threadfence();
                    atomicAdd(&g_phase, 1);
                } else {
                    unsigned target = base + (unsigned)(t + 1);
                    while (*(volatile unsigned*)&g_phase < target) { }
                    __threadfence();
                }
            }
            __syncthreads();
        }
    }
}

// ===========================================================================
// Launch
// ===========================================================================
extern "C" void kernel_launch(void* const* d_in, const int* in_sizes, int n_in,
                              void* d_out, int out_size)
{
    const float* x    = (const float*)d_in[0];
    const float* W    = (const float*)d_in[1];
    const float* bias = (const float*)d_in[2];
    float* out = (float*)d_out;

    cudaFuncSetAttribute(gemm_x_tf32, cudaFuncAttributeMaxDynamicSharedMemorySize,
                         X_SMEM_FLOATS * sizeof(float));
    cudaFuncSetAttribute(rnn_persistent, cudaFuncAttributeMaxDynamicSharedMemorySize,
                         R_SMEM_FLOATS * sizeof(float));

    dim3 g1(DD / X_BN, (TT * BB) / X_BM);   // (8, 512)
    gemm_x_tf32<<<g1, 256, X_SMEM_FLOATS * sizeof(float)>>>(x, W, bias, out);

    rnn_persistent<<<R_NBLK, 512, R_SMEM_FLOATS * sizeof(float)>>>(W, out);
}